// round 9
// baseline (speedup 1.0000x reference)
#include <cuda_runtime.h>
#include <cuda_bf16.h>

// CenterLoss: loss = sum_i clamp(||pred_i - centers[target_i]||^2, 1e-12, 1e12)
//                    + BATCH*(NUM_CLASSES-1)*1e-12
//
// pred [16384,1024] f32, centers [10000,1024] f32, target [16384] i32.
// Output: scalar f32.
//
// R8: single-wave (1024 CTAs, 256 thr, occ 8) like R7, but both rows of a
// warp are streamed with independent accumulators s0/s1 and reduced only at
// the end — no mid-stream shuffle chain serializing the LDG stream.

#define BATCH        16384
#define NUM_CLASSES  10000
#define FEAT_DIM     1024

#define NWARPS        8
#define NTHREADS      (NWARPS * 32)           // 256
#define ROWS_PER_WARP 2
#define GRID          (BATCH / (NWARPS * ROWS_PER_WARP))   // 1024 CTAs — one wave

__device__ float g_partial[GRID];
__device__ int   g_ticket = 0;   // self-resetting

__global__ __launch_bounds__(NTHREADS, 8)
void center_loss_fused(const float* __restrict__ pred,
                       const float* __restrict__ centers,
                       const int* __restrict__ target,
                       float* __restrict__ out)
{
    const int tid  = threadIdx.x;
    const int lane = tid & 31;
    const int wid  = tid >> 5;

    const int row0 = (blockIdx.x * NWARPS + wid) * ROWS_PER_WARP;
    const int row1 = row0 + 1;

    int cls0 = target[row0];
    int cls1 = target[row1];
    cls0 = min(max(cls0, 0), NUM_CLASSES - 1);
    cls1 = min(max(cls1, 0), NUM_CLASSES - 1);

    const float4* p0 = reinterpret_cast<const float4*>(pred    + (size_t)row0 * FEAT_DIM);
    const float4* c0 = reinterpret_cast<const float4*>(centers + (size_t)cls0 * FEAT_DIM);
    const float4* p1 = reinterpret_cast<const float4*>(pred    + (size_t)row1 * FEAT_DIM);
    const float4* c1 = reinterpret_cast<const float4*>(centers + (size_t)cls1 * FEAT_DIM);

    float s0 = 0.0f, s1 = 0.0f;

    // Interleaved stream: both rows' loads form one continuous LDG sequence;
    // accumulators are independent so no cross-row dependency stalls.
    #pragma unroll
    for (int i = 0; i < 8; ++i) {
        float4 pa = __ldg(&p0[lane + i * 32]);
        float4 ca = __ldg(&c0[lane + i * 32]);
        float4 pb = __ldg(&p1[lane + i * 32]);
        float4 cb = __ldg(&c1[lane + i * 32]);

        float dx = pa.x - ca.x, dy = pa.y - ca.y, dz = pa.z - ca.z, dw = pa.w - ca.w;
        s0 = fmaf(dx, dx, s0); s0 = fmaf(dy, dy, s0);
        s0 = fmaf(dz, dz, s0); s0 = fmaf(dw, dw, s0);

        float ex = pb.x - cb.x, ey = pb.y - cb.y, ez = pb.z - cb.z, ew = pb.w - cb.w;
        s1 = fmaf(ex, ex, s1); s1 = fmaf(ey, ey, s1);
        s1 = fmaf(ez, ez, s1); s1 = fmaf(ew, ew, s1);
    }

    // Reduce both rows (paired shuffles pipeline back-to-back).
    #pragma unroll
    for (int off = 16; off > 0; off >>= 1) {
        s0 += __shfl_xor_sync(0xFFFFFFFFu, s0, off);
        s1 += __shfl_xor_sync(0xFFFFFFFFu, s1, off);
    }

    // Per-row clamp (exact reference semantics), then combine.
    float warp_total = fminf(fmaxf(s0, 1e-12f), 1e12f)
                     + fminf(fmaxf(s1, 1e-12f), 1e12f);

    __shared__ float warp_sum[NWARPS];
    if (lane == 0) warp_sum[wid] = warp_total;
    __syncthreads();

    __shared__ bool is_last;
    if (tid == 0) {
        float blocksum = 0.0f;
        #pragma unroll
        for (int i = 0; i < NWARPS; ++i) blocksum += warp_sum[i];
        g_partial[blockIdx.x] = blocksum;
        __threadfence();
        int t = atomicAdd(&g_ticket, 1);
        is_last = (t == GRID - 1);
    }
    __syncthreads();

    // Last CTA: deterministic fixed-order reduction of all 1024 partials.
    if (is_last) {
        __threadfence();  // acquire: see all g_partial writes
        float v = 0.0f;
        #pragma unroll
        for (int i = 0; i < GRID / NTHREADS; ++i)   // 4 per thread, fixed order
            v += g_partial[tid + i * NTHREADS];

        #pragma unroll
        for (int off = 16; off > 0; off >>= 1)
            v += __shfl_xor_sync(0xFFFFFFFFu, v, off);

        __shared__ float red[NWARPS];
        if (lane == 0) red[wid] = v;
        __syncthreads();

        if (wid == 0) {
            float r = (lane < NWARPS) ? red[lane] : 0.0f;
            #pragma unroll
            for (int off = 4; off > 0; off >>= 1)
                r += __shfl_xor_sync(0xFFFFFFFFu, r, off);
            if (lane == 0) {
                const float masked_const =
                    (float)((double)BATCH * (double)(NUM_CLASSES - 1) * 1e-12);
                out[0] = r + masked_const;
                g_ticket = 0;   // reset for next graph replay
            }
        }
    }
}

extern "C" void kernel_launch(void* const* d_in, const int* in_sizes, int n_in,
                              void* d_out, int out_size)
{
    const float* pred    = (const float*)d_in[0];
    const float* centers = (const float*)d_in[1];
    const int*   target  = (const int*)d_in[2];
    float*       out     = (float*)d_out;

    center_loss_fused<<<GRID, NTHREADS>>>(pred, centers, target, out);
}